// round 16
// baseline (speedup 1.0000x reference)
#include <cuda_runtime.h>
#include <cuda_fp16.h>
#include <math.h>
#include <stdint.h>

#define N_TOK   8192
#define IN_LEN  512
#define OUT_LEN 512
#define NE      8
#define NI      16
#define NPAIR   (N_TOK*2)
#define MAX_TILES (NPAIR/128 + NE)   // 136
#define NB_CONVW (NE*16*16)          // 2048
#define NB_BETA  (NE*4)              // 32
#define NB_ROUTE (N_TOK/32)          // 256 (32 tokens/block, tail-scheduled)
#define FUSED_SMEM 49152             // 16KB gate + 32KB stage (16 tokens)

// ---------------- device scratch ----------------
__device__ float g_bet[NE*OUT_LEN];
__device__ int   g_sel[NPAIR];
__device__ float g_rw[NPAIR];
__device__ int   g_cursor[NE];                 // zero-init; re-zeroed by k_final
__device__ int   g_list[NE*N_TOK];
__device__ float g_lcoef[NE*N_TOK];
__device__ int   g_tslot[NPAIR];
__device__ __half g_stage[(size_t)NE*N_TOK*OUT_LEN];
__device__ __half g_wh[(size_t)NE*OUT_LEN*IN_LEN];   // w fp16, [E,N,K]
__device__ __half g_xh[(size_t)N_TOK*IN_LEN];        // x hi fp16
__device__ __half g_xl[(size_t)N_TOK*IN_LEN];        // x lo fp16

// ---------------- PTX helpers ----------------
__device__ __forceinline__ uint32_t smem_u32(const void* p) {
    uint32_t a;
    asm("{ .reg .u64 t; cvta.to.shared.u64 t, %1; cvt.u32.u64 %0, t; }" : "=r"(a) : "l"(p));
    return a;
}
__device__ __forceinline__ void cpasync16(uint32_t dst, const void* src) {
    asm volatile("cp.async.cg.shared.global [%0], [%1], 16;" :: "r"(dst), "l"(src));
}
__device__ __forceinline__ void cp_commit() { asm volatile("cp.async.commit_group;" ::: "memory"); }
__device__ __forceinline__ void ldsm4(uint32_t* r, uint32_t addr) {
    asm volatile("ldmatrix.sync.aligned.m8n8.x4.shared.b16 {%0,%1,%2,%3}, [%4];"
                 : "=r"(r[0]), "=r"(r[1]), "=r"(r[2]), "=r"(r[3]) : "r"(addr));
}
__device__ __forceinline__ void mma16816(float* d, const uint32_t* a, const uint32_t* b) {
    asm volatile(
        "mma.sync.aligned.m16n8k16.row.col.f32.f16.f16.f32 "
        "{%0,%1,%2,%3}, {%4,%5,%6,%7}, {%8,%9}, {%0,%1,%2,%3};"
        : "+f"(d[0]), "+f"(d[1]), "+f"(d[2]), "+f"(d[3])
        : "r"(a[0]), "r"(a[1]), "r"(a[2]), "r"(a[3]), "r"(b[0]), "r"(b[1]));
}
__device__ __forceinline__ uint32_t pkhf(float a, float b) {
    __half2 h = __floats2half2_rn(a, b);
    return *(uint32_t*)&h;
}

// ---- K_fused: convw [0,2048) | beta [2048,2080) | route [2080,2336) (tail) ------
__global__ __launch_bounds__(512, 3) void k_fused(const float* __restrict__ ew,
                                                  const float* __restrict__ ins,
                                                  const float* __restrict__ rmod,
                                                  const float* __restrict__ gammaw,
                                                  const float* __restrict__ betaw,
                                                  const float* __restrict__ eb,
                                                  const float* __restrict__ x,
                                                  const float* __restrict__ gatew) {
    extern __shared__ float dsm[];
    __shared__ float s_mean[512];
    __shared__ float s_red[512];
    __shared__ float s_rg[NE], s_gm[NE];
    int bi = blockIdx.x;
    int tid = threadIdx.x;

    if (bi < NB_CONVW) {
        // ---- convw: expert_w [E,K,N] -> fp16 [E,N,K] ----
        float (*t)[33] = (float(*)[33])dsm;
        int e  = bi >> 8;
        int r8 = bi & 255;
        int nb = (r8 >> 4) * 32;
        int kb = (r8 & 15) * 32;
        const float* src = ew + ((size_t)e*IN_LEN + kb)*OUT_LEN + nb;
        int tx = tid & 31;
#pragma unroll
        for (int i = tid >> 5; i < 32; i += 16)
            t[i][tx] = src[(size_t)i*OUT_LEN + tx];
        __syncthreads();
        if (tid < 256) {
            int r  = tid >> 3;
            int kq = tid & 7;
            uint2 hp = make_uint2(pkhf(t[kq*4+0][r], t[kq*4+1][r]),
                                  pkhf(t[kq*4+2][r], t[kq*4+3][r]));
            size_t o = ((size_t)e*OUT_LEN + nb + r)*IN_LEN + kb + kq*4;
            *(uint2*)(g_wh + o) = hp;
        }
    } else if (bi < NB_CONVW + NB_BETA) {
        // ---- beta: self-contained ----
        int idx = bi - NB_CONVW;
        int e = idx >> 2;
        int d = (idx & 3)*128 + (tid & 127);
        float mi = 0.f;
#pragma unroll
        for (int n = 0; n < NI; n++) mi += ins[n*OUT_LEN + tid];
        mi *= (1.f/NI);
        s_mean[tid] = mi;
        s_red[tid]  = mi * gammaw[e*OUT_LEN + tid];
        __syncthreads();
#pragma unroll
        for (int s = 256; s > 0; s >>= 1) {
            if (tid < s) s_red[tid] += s_red[tid + s];
            __syncthreads();
        }
        float gam = s_red[0];
        __syncthreads();
        int hg = tid >> 7;
        const float* bw = betaw + (size_t)e*OUT_LEN*OUT_LEN + d;
        float s = 0.f;
#pragma unroll 8
        for (int h = hg*128; h < hg*128 + 128; h++)
            s += s_mean[h] * bw[(size_t)h*OUT_LEN];
        s_red[tid] = s;
        __syncthreads();
        if (hg == 0) {
            float tot = s_red[tid] + s_red[tid+128] + s_red[tid+256] + s_red[tid+384];
            g_bet[e*OUT_LEN + d] = tot + gam * eb[e*OUT_LEN + d];
        }
    } else {
        // ---- route: 32 tokens/block; pass 1 (16 tok) cp.async-staged,
        //      pass 2 (16 tok) direct register loads. 48KB smem -> 3 CTAs/SM. ----
        uint32_t sb = smem_u32(dsm);
        int rb = bi - (NB_CONVW + NB_BETA);
        int tb = rb * 32;
        int lane = tid & 31, wid = tid >> 5;

        // stage first 16 tokens (32 KB): 4 slots/thread
#pragma unroll
        for (int p = 0; p < 4; p++) {
            int slot = tid + p*512;
            cpasync16(sb + 16384 + slot*16,
                      x + (size_t)(tb + (slot >> 7))*IN_LEN + (slot & 127)*4);
        }
        cp_commit();

        // gate transpose fill (overlaps async loads)
        for (int i = tid; i < IN_LEN*NE; i += 512)
            dsm[(i & 7)*IN_LEN + (i >> 3)] = gatew[i];

        // local mean_ins, rgamma, gam
        float mi = 0.f;
#pragma unroll
        for (int n = 0; n < NI; n++) mi += ins[n*OUT_LEN + tid];
        mi *= (1.f/NI);
        s_mean[tid] = mi;
        __syncthreads();
        {
            int eg = tid >> 6, li = tid & 63;
            float a = 0.f, b = 0.f;
#pragma unroll
            for (int j = 0; j < 8; j++) {
                int h = li + j*64;
                float m = s_mean[h];
                a += m * rmod[h*NE + eg];
                b += m * gammaw[eg*OUT_LEN + h];
            }
#pragma unroll
            for (int o = 16; o > 0; o >>= 1) {
                a += __shfl_xor_sync(0xffffffffu, a, o);
                b += __shfl_xor_sync(0xffffffffu, b, o);
            }
            if ((li & 31) == 0) {
                s_red[eg*2 + (li >> 5)]      = a;
                s_red[16 + eg*2 + (li >> 5)] = b;
            }
        }
        __syncthreads();
        if (tid < NE) {
            s_rg[tid] = s_red[tid*2]      + s_red[tid*2 + 1];
            s_gm[tid] = s_red[16 + tid*2] + s_red[16 + tid*2 + 1];
        }

        asm volatile("cp.async.wait_group 0;" ::: "memory");
        __syncthreads();

#pragma unroll
        for (int s = 0; s < 2; s++) {
            int t = tb + s*16 + wid;
            // pass 0: token data from smem stage; pass 1: direct global loads
            float4 v[4];
            if (s == 0) {
                const float* xt = dsm + 4096 + wid*IN_LEN;
#pragma unroll
                for (int j = 0; j < 4; j++) v[j] = *(const float4*)(xt + j*128 + lane*4);
            } else {
                const float4* xr = (const float4*)(x + (size_t)t*IN_LEN);
#pragma unroll
                for (int j = 0; j < 4; j++) v[j] = xr[j*32 + lane];   // MLP=4
            }
            float acc[NE];
#pragma unroll
            for (int e = 0; e < NE; e++) acc[e] = 0.f;
#pragma unroll
            for (int j = 0; j < 4; j++) {
                float4 w = v[j];
                __half h0 = __float2half_rn(w.x), h1 = __float2half_rn(w.y);
                __half h2 = __float2half_rn(w.z), h3 = __float2half_rn(w.w);
                uint2 hp;
                hp.x = (uint32_t)__half_as_ushort(h0) | ((uint32_t)__half_as_ushort(h1) << 16);
                hp.y = (uint32_t)__half_as_ushort(h2) | ((uint32_t)__half_as_ushort(h3) << 16);
                uint2 lp = make_uint2(
                    pkhf(w.x - __half2float(h0), w.y - __half2float(h1)),
                    pkhf(w.z - __half2float(h2), w.w - __half2float(h3)));
                size_t xo = (size_t)t*IN_LEN + j*128 + lane*4;
                *(uint2*)(g_xh + xo) = hp;
                *(uint2*)(g_xl + xo) = lp;
#pragma unroll
                for (int e = 0; e < NE; e++) {
                    float4 g = *(const float4*)&dsm[e*IN_LEN + j*128 + lane*4];
                    acc[e] += w.x*g.x + w.y*g.y + w.z*g.z + w.w*g.w;
                }
            }
#pragma unroll
            for (int e = 0; e < NE; e++)
#pragma unroll
                for (int o = 16; o > 0; o >>= 1)
                    acc[e] += __shfl_xor_sync(0xffffffffu, acc[e], o);
            if (lane == 0) {
                float l[NE];
#pragma unroll
                for (int e = 0; e < NE; e++) l[e] = acc[e] + s_rg[e];
                float m = l[0];
#pragma unroll
                for (int e = 1; e < NE; e++) m = fmaxf(m, l[e]);
                float ssum = 0.f;
#pragma unroll
                for (int e = 0; e < NE; e++) ssum += expf(l[e] - m);
                float inv = 1.f / ssum;
                int e0 = 0; float v0 = l[0];
#pragma unroll
                for (int e = 1; e < NE; e++) if (l[e] > v0) { v0 = l[e]; e0 = e; }
                int e1 = -1; float v1 = -INFINITY;
#pragma unroll
                for (int e = 0; e < NE; e++) if (e != e0 && l[e] > v1) { v1 = l[e]; e1 = e; }
                float rw0 = expf(v0 - m) * inv;
                float rw1 = expf(v1 - m) * inv;
                g_sel[2*t] = e0;  g_sel[2*t+1] = e1;
                g_rw[2*t]  = rw0; g_rw[2*t+1]  = rw1;
                int c0 = atomicAdd(&g_cursor[e0], 1);
                int c1 = atomicAdd(&g_cursor[e1], 1);
                int sl0 = e0*N_TOK + c0, sl1 = e1*N_TOK + c1;
                g_list[sl0]  = t;              g_list[sl1]  = t;
                g_lcoef[sl0] = rw0*s_gm[e0];   g_lcoef[sl1] = rw1*s_gm[e1];
                g_tslot[2*t]   = sl0;
                g_tslot[2*t+1] = sl1;
            }
        }
    }
}

// ---------------- K6: HMMA GEMM 128x128, BK=64, 2-stage (round-11 proven) ---------
#define BK        64
#define NCH       (IN_LEN/BK)      // 8
#define ST_AH     0
#define ST_AL     16384
#define ST_B      32768
#define ST_SIZE   49152
#define OFF_TOK   (2*ST_SIZE)      // 98304
#define OFF_COEF  (OFF_TOK + 512)
#define DYN_SMEM  (OFF_COEF + 512) // 99328

__device__ __forceinline__ uint32_t tile_off(int row, int c) {
    return (uint32_t)(row*128 + ((c ^ (row & 7)) << 4));
}

__global__ __launch_bounds__(256, 2) void k_gemm_tc(void) {
    extern __shared__ char smem[];
    int rt = blockIdx.x;
    int e = -1, rbase = 0, nrows = 0;
    {
        int ts = 0;
#pragma unroll
        for (int i = 0; i < NE; i++) {
            int cnt = g_cursor[i];
            int ti = (cnt + 127) >> 7;
            if (e < 0 && rt < ts + ti) {
                int tie = rt - ts;
                e = i; rbase = i*N_TOK + tie*128; nrows = cnt - tie*128;
            }
            ts += ti;
        }
    }
    if (e < 0) return;
    if (nrows > 128) nrows = 128;

    uint32_t sb = smem_u32(smem);
    int tid = threadIdx.x;
    int lane = tid & 31;
    int wid = tid >> 5;
    int wm = wid >> 1;
    int wn = wid & 1;

    int*   s_tok  = (int*)(smem + OFF_TOK);
    float* s_coef = (float*)(smem + OFF_COEF);
    if (tid < 128) {
        s_tok[tid]  = (tid < nrows) ? g_list[rbase + tid]  : g_list[rbase];
        s_coef[tid] = (tid < nrows) ? g_lcoef[rbase + tid] : 0.f;
    }
    __syncthreads();

    int cc = tid & 7;
    int rr[4], tk[4];
    uint32_t dA[4];
#pragma unroll
    for (int p = 0; p < 4; p++) {
        rr[p] = (tid >> 3) + p*32;
        tk[p] = s_tok[rr[p]];
        dA[p] = tile_off(rr[p], cc);
    }
    int j4 = lane >> 3, l7 = lane & 7;
    int krot = wid & 3;

    for (int yp = 0; yp < 2; yp++) {
        int cbase = (blockIdx.y*2 + yp)*128;
        const __half* whp = g_wh + ((size_t)e*OUT_LEN + cbase)*IN_LEN;

        auto issue = [&](uint32_t st, int k0) {
#pragma unroll
            for (int p = 0; p < 4; p++) {
                cpasync16(st + ST_AH + dA[p], g_xh + (size_t)tk[p]*IN_LEN + k0 + cc*8);
                cpasync16(st + ST_AL + dA[p], g_xl + (size_t)tk[p]*IN_LEN + k0 + cc*8);
                cpasync16(st + ST_B  + dA[p], whp + (size_t)rr[p]*IN_LEN + k0 + cc*8);
            }
        };

        issue(sb, 0);
        cp_commit();

        float acc[2][8][4];
#pragma unroll
        for (int mb = 0; mb < 2; mb++)
#pragma unroll
            for (int nb = 0; nb < 8; nb++)
#pragma unroll
                for (int j = 0; j < 4; j++) acc[mb][nb][j] = 0.f;

        for (int ch = 0; ch < NCH; ch++) {
            asm volatile("cp.async.wait_group 0;" ::: "memory");
            __syncthreads();
            if (ch + 1 < NCH) {
                issue(sb + ((ch + 1) & 1)*ST_SIZE, (ch + 1)*BK);
                cp_commit();
            }
            uint32_t st = sb + (ch & 1)*ST_SIZE;
#pragma unroll
            for (int kk = 0; kk < 4; kk++) {
                int k16 = (kk + krot) & 3;
                uint32_t ah[2][4], al[2][4];
#pragma unroll
                for (int mb = 0; mb < 2; mb++) {
                    int row = wm*32 + mb*16 + ((j4 & 1) << 3) + l7;
                    int c   = k16*2 + (j4 >> 1);
                    uint32_t o = tile_off(row, c);
                    ldsm4(ah[mb], st + ST_AH + o);
                    ldsm4(al[mb], st + ST_AL + o);
                }
#pragma unroll
                for (int p = 0; p < 4; p++) {
                    int row = wn*64 + p*16 + ((j4 >> 1) << 3) + l7;
                    int c   = k16*2 + (j4 & 1);
                    uint32_t o = tile_off(row, c);
                    uint32_t bh[4];
                    ldsm4(bh, st + ST_B + o);
#pragma unroll
                    for (int mb = 0; mb < 2; mb++)
#pragma unroll
                        for (int h = 0; h < 2; h++)
                            mma16816(acc[mb][2*p + h], ah[mb], &bh[h*2]);
#pragma unroll
                    for (int mb = 0; mb < 2; mb++)
#pragma unroll
                        for (int h = 0; h < 2; h++)
                            mma16816(acc[mb][2*p + h], al[mb], &bh[h*2]);
                }
            }
        }

        int rl_lo = wm*32 + (lane >> 2);
        int ccc   = cbase + wn*64 + (lane & 3)*2;
#pragma unroll
        for (int mb = 0; mb < 2; mb++) {
#pragma unroll
            for (int half = 0; half < 2; half++) {
                int rl = rl_lo + mb*16 + half*8;
                if (rl < nrows) {
                    float cf = s_coef[rl];
                    __half* dst = g_stage + (size_t)(rbase + rl)*OUT_LEN + ccc;
#pragma unroll
                    for (int nb = 0; nb < 8; nb++)
                        *(uint32_t*)(dst + nb*8) =
                            pkhf(cf*acc[mb][nb][half*2], cf*acc[mb][nb][half*2+1]);
                }
            }
        }
    }
}

// ---------------- K7: compose; re-zeroes cursors for the next call ----------------
__global__ __launch_bounds__(256) void k_final(float* __restrict__ out) {
    if (blockIdx.x == 0 && threadIdx.x < NE) g_cursor[threadIdx.x] = 0;
    int t = blockIdx.x*2 + (threadIdx.x >> 7);
    int i = threadIdx.x & 127;
    int e0 = g_sel[2*t], e1 = g_sel[2*t+1];
    float r0 = g_rw[2*t], r1 = g_rw[2*t+1];
    int s0 = g_tslot[2*t], s1 = g_tslot[2*t+1];
    float4 b0 = *(const float4*)(g_bet + e0*OUT_LEN + i*4);
    float4 b1 = *(const float4*)(g_bet + e1*OUT_LEN + i*4);
    uint2 u0 = *(const uint2*)(g_stage + (size_t)s0*OUT_LEN + i*4);
    uint2 u1 = *(const uint2*)(g_stage + (size_t)s1*OUT_LEN + i*4);
    float2 a0 = __half22float2(*(__half2*)&u0.x);
    float2 a1 = __half22float2(*(__half2*)&u0.y);
    float2 c0 = __half22float2(*(__half2*)&u1.x);
    float2 c1 = __half22float2(*(__half2*)&u1.y);
    float4 o;
    o.x = fmaf(r0, b0.x, fmaf(r1, b1.x, a0.x + c0.x));
    o.y = fmaf(r0, b0.y, fmaf(r1, b1.y, a0.y + c0.y));
    o.z = fmaf(r0, b0.z, fmaf(r1, b1.z, a1.x + c1.x));
    o.w = fmaf(r0, b0.w, fmaf(r1, b1.w, a1.y + c1.y));
    *(float4*)(out + (size_t)t*OUT_LEN + i*4) = o;
}

// ---------------- launch ----------------
extern "C" void kernel_launch(void* const* d_in, const int* in_sizes, int n_in,
                              void* d_out, int out_size) {
    const float* x      = (const float*)d_in[0];
    const float* ins    = (const float*)d_in[1];
    const float* gatew  = (const float*)d_in[2];
    const float* ew     = (const float*)d_in[3];
    const float* eb     = (const float*)d_in[4];
    const float* gammaw = (const float*)d_in[5];
    const float* betaw  = (const float*)d_in[6];
    const float* rmod   = (const float*)d_in[7];
    float* out = (float*)d_out;

    cudaFuncSetAttribute(k_fused,   cudaFuncAttributeMaxDynamicSharedMemorySize, FUSED_SMEM);
    cudaFuncSetAttribute(k_gemm_tc, cudaFuncAttributeMaxDynamicSharedMemorySize, DYN_SMEM);

    k_fused  <<<NB_CONVW + NB_BETA + NB_ROUTE, 512, FUSED_SMEM>>>(
                 ew, ins, rmod, gammaw, betaw, eb, x, gatew);
    k_gemm_tc<<<dim3(MAX_TILES, 2), 256, DYN_SMEM>>>();
    k_final  <<<N_TOK/2, 256>>>(out);
}

// round 17
// speedup vs baseline: 1.3346x; 1.3346x over previous
#include <cuda_runtime.h>
#include <cuda_fp16.h>
#include <math.h>
#include <stdint.h>

#define N_TOK   8192
#define IN_LEN  512
#define OUT_LEN 512
#define NE      8
#define NI      16
#define NPAIR   (N_TOK*2)
#define MAX_TILES (NPAIR/128 + NE)   // 136
#define NB_CONVW (NE*16*16)          // 2048
#define NB_BETA  (NE*4)              // 32
#define NB_ROUTE (N_TOK/32)          // 256
#define FUSED_SMEM 81920             // 4096 gate + 2*8192 stage floats

// ---------------- device scratch ----------------
__device__ float g_bet[NE*OUT_LEN];
__device__ int   g_sel[NPAIR];
__device__ float g_rw[NPAIR];
__device__ int   g_cursor[NE];                 // zero-init; re-zeroed by k_final
__device__ int   g_list[NE*N_TOK];
__device__ float g_lcoef[NE*N_TOK];
__device__ int   g_tslot[NPAIR];
__device__ __half g_stage[(size_t)NE*N_TOK*OUT_LEN];
__device__ __half g_wh[(size_t)NE*OUT_LEN*IN_LEN];   // w fp16, [E,N,K]
__device__ __half g_xh[(size_t)N_TOK*IN_LEN];        // x hi fp16
__device__ __half g_xl[(size_t)N_TOK*IN_LEN];        // x lo fp16

// ---------------- PTX helpers ----------------
__device__ __forceinline__ uint32_t smem_u32(const void* p) {
    uint32_t a;
    asm("{ .reg .u64 t; cvta.to.shared.u64 t, %1; cvt.u32.u64 %0, t; }" : "=r"(a) : "l"(p));
    return a;
}
__device__ __forceinline__ void cpasync16(uint32_t dst, const void* src) {
    asm volatile("cp.async.cg.shared.global [%0], [%1], 16;" :: "r"(dst), "l"(src));
}
__device__ __forceinline__ void cp_commit() { asm volatile("cp.async.commit_group;" ::: "memory"); }
__device__ __forceinline__ void ldsm4(uint32_t* r, uint32_t addr) {
    asm volatile("ldmatrix.sync.aligned.m8n8.x4.shared.b16 {%0,%1,%2,%3}, [%4];"
                 : "=r"(r[0]), "=r"(r[1]), "=r"(r[2]), "=r"(r[3]) : "r"(addr));
}
__device__ __forceinline__ void mma16816(float* d, const uint32_t* a, const uint32_t* b) {
    asm volatile(
        "mma.sync.aligned.m16n8k16.row.col.f32.f16.f16.f32 "
        "{%0,%1,%2,%3}, {%4,%5,%6,%7}, {%8,%9}, {%0,%1,%2,%3};"
        : "+f"(d[0]), "+f"(d[1]), "+f"(d[2]), "+f"(d[3])
        : "r"(a[0]), "r"(a[1]), "r"(a[2]), "r"(a[3]), "r"(b[0]), "r"(b[1]));
}
__device__ __forceinline__ uint32_t pkhf(float a, float b) {
    __half2 h = __floats2half2_rn(a, b);
    return *(uint32_t*)&h;
}

// ---------------- K_fused: convw [0,2048) | beta [2048,2080) | route [2080,2336) --
__global__ __launch_bounds__(512) void k_fused(const float* __restrict__ ew,
                                               const float* __restrict__ ins,
                                               const float* __restrict__ rmod,
                                               const float* __restrict__ gammaw,
                                               const float* __restrict__ betaw,
                                               const float* __restrict__ eb,
                                               const float* __restrict__ x,
                                               const float* __restrict__ gatew) {
    extern __shared__ float dsm[];
    __shared__ float s_mean[512];
    __shared__ float s_red[512];
    __shared__ float s_rg[NE], s_gm[NE];
    int bi = blockIdx.x;
    int tid = threadIdx.x;

    if (bi < NB_CONVW) {
        // ---- convw: expert_w [E,K,N] -> fp16 [E,N,K] ----
        float (*t)[33] = (float(*)[33])dsm;
        int e  = bi >> 8;
        int r8 = bi & 255;
        int nb = (r8 >> 4) * 32;
        int kb = (r8 & 15) * 32;
        const float* src = ew + ((size_t)e*IN_LEN + kb)*OUT_LEN + nb;
        int tx = tid & 31;
#pragma unroll
        for (int i = tid >> 5; i < 32; i += 16)
            t[i][tx] = src[(size_t)i*OUT_LEN + tx];
        __syncthreads();
        if (tid < 256) {
            int r  = tid >> 3;
            int kq = tid & 7;
            uint2 hp = make_uint2(pkhf(t[kq*4+0][r], t[kq*4+1][r]),
                                  pkhf(t[kq*4+2][r], t[kq*4+3][r]));
            size_t o = ((size_t)e*OUT_LEN + nb + r)*IN_LEN + kb + kq*4;
            *(uint2*)(g_wh + o) = hp;
        }
    } else if (bi < NB_CONVW + NB_BETA) {
        // ---- beta: self-contained ----
        int idx = bi - NB_CONVW;
        int e = idx >> 2;
        int d = (idx & 3)*128 + (tid & 127);
        float mi = 0.f;
#pragma unroll
        for (int n = 0; n < NI; n++) mi += ins[n*OUT_LEN + tid];
        mi *= (1.f/NI);
        s_mean[tid] = mi;
        s_red[tid]  = mi * gammaw[e*OUT_LEN + tid];
        __syncthreads();
#pragma unroll
        for (int s = 256; s > 0; s >>= 1) {
            if (tid < s) s_red[tid] += s_red[tid + s];
            __syncthreads();
        }
        float gam = s_red[0];
        __syncthreads();
        int hg = tid >> 7;
        const float* bw = betaw + (size_t)e*OUT_LEN*OUT_LEN + d;
        float s = 0.f;
#pragma unroll 8
        for (int h = hg*128; h < hg*128 + 128; h++)
            s += s_mean[h] * bw[(size_t)h*OUT_LEN];
        s_red[tid] = s;
        __syncthreads();
        if (hg == 0) {
            float tot = s_red[tid] + s_red[tid+128] + s_red[tid+256] + s_red[tid+384];
            g_bet[e*OUT_LEN + d] = tot + gam * eb[e*OUT_LEN + d];
        }
    } else {
        // ---- route: 32 tokens/block, local rgamma/gam, inline scatter ----
        uint32_t sb = smem_u32(dsm);
        int rb = bi - (NB_CONVW + NB_BETA);
        int tb = rb * 32;
        int lane = tid & 31, wid = tid >> 5;

        // stage both halves of x (2 x 16 tokens x 2KB) via cp.async
#pragma unroll
        for (int p = 0; p < 4; p++) {
            int slot = tid + p*512;
            cpasync16(sb + 16384 + slot*16,
                      x + (size_t)(tb + (slot >> 7))*IN_LEN + (slot & 127)*4);
        }
        cp_commit();
#pragma unroll
        for (int p = 0; p < 4; p++) {
            int slot = tid + p*512;
            cpasync16(sb + 49152 + slot*16,
                      x + (size_t)(tb + 16 + (slot >> 7))*IN_LEN + (slot & 127)*4);
        }
        cp_commit();

        // gate transpose fill (overlaps async loads)
        for (int i = tid; i < IN_LEN*NE; i += 512)
            dsm[(i & 7)*IN_LEN + (i >> 3)] = gatew[i];

        // local mean_ins, rgamma, gam (fixed deterministic reduction)
        float mi = 0.f;
#pragma unroll
        for (int n = 0; n < NI; n++) mi += ins[n*OUT_LEN + tid];
        mi *= (1.f/NI);
        s_mean[tid] = mi;
        __syncthreads();
        {
            int eg = tid >> 6, li = tid & 63;
            float a = 0.f, b = 0.f;
#pragma unroll
            for (int j = 0; j < 8; j++) {
                int h = li + j*64;
                float m = s_mean[h];
                a += m * rmod[h*NE + eg];
                b += m * gammaw[eg*OUT_LEN + h];
            }
#pragma unroll
            for (int o = 16; o > 0; o >>= 1) {
                a += __shfl_xor_sync(0xffffffffu, a, o);
                b += __shfl_xor_sync(0xffffffffu, b, o);
            }
            if ((li & 31) == 0) {
                s_red[eg*2 + (li >> 5)]      = a;
                s_red[16 + eg*2 + (li >> 5)] = b;
            }
        }
        __syncthreads();
        if (tid < NE) {
            s_rg[tid] = s_red[tid*2]      + s_red[tid*2 + 1];
            s_gm[tid] = s_red[16 + tid*2] + s_red[16 + tid*2 + 1];
        }

        asm volatile("cp.async.wait_group 1;" ::: "memory");
        __syncthreads();

#pragma unroll
        for (int s = 0; s < 2; s++) {
            if (s == 1) {
                asm volatile("cp.async.wait_group 0;" ::: "memory");
                __syncthreads();
            }
            int t = tb + s*16 + wid;
            const float* xt = dsm + 4096 + s*8192 + wid*IN_LEN;
            float acc[NE];
#pragma unroll
            for (int e = 0; e < NE; e++) acc[e] = 0.f;
#pragma unroll
            for (int j = 0; j < 4; j++) {
                float4 w = *(const float4*)(xt + j*128 + lane*4);
                __half h0 = __float2half_rn(w.x), h1 = __float2half_rn(w.y);
                __half h2 = __float2half_rn(w.z), h3 = __float2half_rn(w.w);
                uint2 hp;
                hp.x = (uint32_t)__half_as_ushort(h0) | ((uint32_t)__half_as_ushort(h1) << 16);
                hp.y = (uint32_t)__half_as_ushort(h2) | ((uint32_t)__half_as_ushort(h3) << 16);
                uint2 lp = make_uint2(
                    pkhf(w.x - __half2float(h0), w.y - __half2float(h1)),
                    pkhf(w.z - __half2float(h2), w.w - __half2float(h3)));
                size_t xo = (size_t)t*IN_LEN + j*128 + lane*4;
                *(uint2*)(g_xh + xo) = hp;
                *(uint2*)(g_xl + xo) = lp;
#pragma unroll
                for (int e = 0; e < NE; e++) {
                    float4 g = *(const float4*)&dsm[e*IN_LEN + j*128 + lane*4];
                    acc[e] += w.x*g.x + w.y*g.y + w.z*g.z + w.w*g.w;
                }
            }
#pragma unroll
            for (int e = 0; e < NE; e++)
#pragma unroll
                for (int o = 16; o > 0; o >>= 1)
                    acc[e] += __shfl_xor_sync(0xffffffffu, acc[e], o);
            if (lane == 0) {
                float l[NE];
#pragma unroll
                for (int e = 0; e < NE; e++) l[e] = acc[e] + s_rg[e];
                float m = l[0];
#pragma unroll
                for (int e = 1; e < NE; e++) m = fmaxf(m, l[e]);
                float ssum = 0.f;
#pragma unroll
                for (int e = 0; e < NE; e++) ssum += expf(l[e] - m);
                float inv = 1.f / ssum;
                int e0 = 0; float v0 = l[0];
#pragma unroll
                for (int e = 1; e < NE; e++) if (l[e] > v0) { v0 = l[e]; e0 = e; }
                int e1 = -1; float v1 = -INFINITY;
#pragma unroll
                for (int e = 0; e < NE; e++) if (e != e0 && l[e] > v1) { v1 = l[e]; e1 = e; }
                float rw0 = expf(v0 - m) * inv;
                float rw1 = expf(v1 - m) * inv;
                g_sel[2*t] = e0;  g_sel[2*t+1] = e1;
                g_rw[2*t]  = rw0; g_rw[2*t+1]  = rw1;
                int c0 = atomicAdd(&g_cursor[e0], 1);
                int c1 = atomicAdd(&g_cursor[e1], 1);
                int sl0 = e0*N_TOK + c0, sl1 = e1*N_TOK + c1;
                g_list[sl0]  = t;              g_list[sl1]  = t;
                g_lcoef[sl0] = rw0*s_gm[e0];   g_lcoef[sl1] = rw1*s_gm[e1];
                g_tslot[2*t]   = sl0;
                g_tslot[2*t+1] = sl1;
            }
        }
    }
}

// ---------------- K6: HMMA GEMM 128x128, BK=64, 2-stage, fp16 2-split -------------
#define BK        64
#define NCH       (IN_LEN/BK)      // 8
#define ST_AH     0
#define ST_AL     16384
#define ST_B      32768
#define ST_SIZE   49152
#define OFF_TOK   (2*ST_SIZE)      // 98304
#define OFF_COEF  (OFF_TOK + 512)
#define DYN_SMEM  (OFF_COEF + 512) // 99328

__device__ __forceinline__ uint32_t tile_off(int row, int c) {
    return (uint32_t)(row*128 + ((c ^ (row & 7)) << 4));
}

__global__ __launch_bounds__(256, 2) void k_gemm_tc(void) {
    extern __shared__ char smem[];
    int rt = blockIdx.x;
    int e = -1, rbase = 0, nrows = 0;
    {
        int ts = 0;
#pragma unroll
        for (int i = 0; i < NE; i++) {
            int cnt = g_cursor[i];
            int ti = (cnt + 127) >> 7;
            if (e < 0 && rt < ts + ti) {
                int tie = rt - ts;
                e = i; rbase = i*N_TOK + tie*128; nrows = cnt - tie*128;
            }
            ts += ti;
        }
    }
    if (e < 0) return;
    if (nrows > 128) nrows = 128;

    uint32_t sb = smem_u32(smem);
    int tid = threadIdx.x;
    int lane = tid & 31;
    int wid = tid >> 5;
    int wm = wid >> 1;
    int wn = wid & 1;

    int*   s_tok  = (int*)(smem + OFF_TOK);
    float* s_coef = (float*)(smem + OFF_COEF);
    if (tid < 128) {
        s_tok[tid]  = (tid < nrows) ? g_list[rbase + tid]  : g_list[rbase];
        s_coef[tid] = (tid < nrows) ? g_lcoef[rbase + tid] : 0.f;
    }
    __syncthreads();

    int cc = tid & 7;
    int rr[4], tk[4];
    uint32_t dA[4];
#pragma unroll
    for (int p = 0; p < 4; p++) {
        rr[p] = (tid >> 3) + p*32;
        tk[p] = s_tok[rr[p]];
        dA[p] = tile_off(rr[p], cc);
    }
    int j4 = lane >> 3, l7 = lane & 7;
    int krot = wid & 3;   // per-warp k16 rotation to stagger LDSM bursts

    for (int yp = 0; yp < 2; yp++) {
        int cbase = (blockIdx.y*2 + yp)*128;
        const __half* whp = g_wh + ((size_t)e*OUT_LEN + cbase)*IN_LEN;

        auto issue = [&](uint32_t st, int k0) {
#pragma unroll
            for (int p = 0; p < 4; p++) {
                cpasync16(st + ST_AH + dA[p], g_xh + (size_t)tk[p]*IN_LEN + k0 + cc*8);
                cpasync16(st + ST_AL + dA[p], g_xl + (size_t)tk[p]*IN_LEN + k0 + cc*8);
                cpasync16(st + ST_B  + dA[p], whp + (size_t)rr[p]*IN_LEN + k0 + cc*8);
            }
        };

        issue(sb, 0);
        cp_commit();

        float acc[2][8][4];
#pragma unroll
        for (int mb = 0; mb < 2; mb++)
#pragma unroll
            for (int nb = 0; nb < 8; nb++)
#pragma unroll
                for (int j = 0; j < 4; j++) acc[mb][nb][j] = 0.f;

        for (int ch = 0; ch < NCH; ch++) {
            asm volatile("cp.async.wait_group 0;" ::: "memory");
            __syncthreads();
            if (ch + 1 < NCH) {
                issue(sb + ((ch + 1) & 1)*ST_SIZE, (ch + 1)*BK);
                cp_commit();
            }
            uint32_t st = sb + (ch & 1)*ST_SIZE;
#pragma unroll
            for (int kk = 0; kk < 4; kk++) {
                int k16 = (kk + krot) & 3;
                uint32_t ah[2][4], al[2][4];
#pragma unroll
                for (int mb = 0; mb < 2; mb++) {
                    int row = wm*32 + mb*16 + ((j4 & 1) << 3) + l7;
                    int c   = k16*2 + (j4 >> 1);
                    uint32_t o = tile_off(row, c);
                    ldsm4(ah[mb], st + ST_AH + o);
                    ldsm4(al[mb], st + ST_AL + o);
                }
#pragma unroll
                for (int p = 0; p < 4; p++) {
                    int row = wn*64 + p*16 + ((j4 >> 1) << 3) + l7;
                    int c   = k16*2 + (j4 & 1);
                    uint32_t o = tile_off(row, c);
                    uint32_t bh[4];
                    ldsm4(bh, st + ST_B + o);
#pragma unroll
                    for (int mb = 0; mb < 2; mb++)
#pragma unroll
                        for (int h = 0; h < 2; h++)
                            mma16816(acc[mb][2*p + h], ah[mb], &bh[h*2]);
#pragma unroll
                    for (int mb = 0; mb < 2; mb++)
#pragma unroll
                        for (int h = 0; h < 2; h++)
                            mma16816(acc[mb][2*p + h], al[mb], &bh[h*2]);
                }
            }
        }

        int rl_lo = wm*32 + (lane >> 2);
        int ccc   = cbase + wn*64 + (lane & 3)*2;
#pragma unroll
        for (int mb = 0; mb < 2; mb++) {
#pragma unroll
            for (int half = 0; half < 2; half++) {
                int rl = rl_lo + mb*16 + half*8;
                if (rl < nrows) {
                    float cf = s_coef[rl];
                    __half* dst = g_stage + (size_t)(rbase + rl)*OUT_LEN + ccc;
#pragma unroll
                    for (int nb = 0; nb < 8; nb++)
                        *(uint32_t*)(dst + nb*8) =
                            pkhf(cf*acc[mb][nb][half*2], cf*acc[mb][nb][half*2+1]);
                }
            }
        }
    }
}

// ---------------- K7: compose; re-zeroes cursors for the next call ----------------
__global__ __launch_bounds__(256) void k_final(float* __restrict__ out) {
    if (blockIdx.x == 0 && threadIdx.x < NE) g_cursor[threadIdx.x] = 0;
    int t = blockIdx.x*2 + (threadIdx.x >> 7);
    int i = threadIdx.x & 127;
    int e0 = g_sel[2*t], e1 = g_sel[2*t+1];
    float r0 = g_rw[2*t], r1 = g_rw[2*t+1];
    int s0 = g_tslot[2*t], s1 = g_tslot[2*t+1];
    float4 b0 = *(const float4*)(g_bet + e0*OUT_LEN + i*4);
    float4 b1 = *(const float4*)(g_bet + e1*OUT_LEN + i*4);
    uint2 u0 = *(const uint2*)(g_stage + (size_t)s0*OUT_LEN + i*4);
    uint2 u1 = *(const uint2*)(g_stage + (size_t)s1*OUT_LEN + i*4);
    float2 a0 = __half22float2(*(__half2*)&u0.x);
    float2 a1 = __half22float2(*(__half2*)&u0.y);
    float2 c0 = __half22float2(*(__half2*)&u1.x);
    float2 c1 = __half22float2(*(__half2*)&u1.y);
    float4 o;
    o.x = fmaf(r0, b0.x, fmaf(r1, b1.x, a0.x + c0.x));
    o.y = fmaf(r0, b0.y, fmaf(r1, b1.y, a0.y + c0.y));
    o.z = fmaf(r0, b0.z, fmaf(r1, b1.z, a1.x + c1.x));
    o.w = fmaf(r0, b0.w, fmaf(r1, b1.w, a1.y + c1.y));
    *(float4*)(out + (size_t)t*OUT_LEN + i*4) = o;
}

// ---------------- launch ----------------
extern "C" void kernel_launch(void* const* d_in, const int* in_sizes, int n_in,
                              void* d_out, int out_size) {
    const float* x      = (const float*)d_in[0];
    const float* ins    = (const float*)d_in[1];
    const float* gatew  = (const float*)d_in[2];
    const float* ew     = (const float*)d_in[3];
    const float* eb     = (const float*)d_in[4];
    const float* gammaw = (const float*)d_in[5];
    const float* betaw  = (const float*)d_in[6];
    const float* rmod   = (const float*)d_in[7];
    float* out = (float*)d_out;

    cudaFuncSetAttribute(k_fused,   cudaFuncAttributeMaxDynamicSharedMemorySize, FUSED_SMEM);
    cudaFuncSetAttribute(k_gemm_tc, cudaFuncAttributeMaxDynamicSharedMemorySize, DYN_SMEM);

    k_fused  <<<NB_CONVW + NB_BETA + NB_ROUTE, 512, FUSED_SMEM>>>(
                 ew, ins, rmod, gammaw, betaw, eb, x, gatew);
    k_gemm_tc<<<dim3(MAX_TILES, 2), 256, DYN_SMEM>>>();
    k_final  <<<N_TOK/2, 256>>>(out);
}